// round 8
// baseline (speedup 1.0000x reference)
#include <cuda_runtime.h>
#include <cuda_fp16.h>
#include <cstdint>

// COO SpMM: out[row[e], :] += values[e] * b[col[e], :]
// indices: [2, E] int32 or int64 (runtime-detected); values: f32 [E];
// b: f32 [N, 128]; out: f32 [N, 128].
//
// R8: TWO kernels. build = (b->fp16 convert || bucket scatter, split blocks).
// spmm = warp-per-row gather+accumulate, inline overflow, and SELF-CLEANING:
// zeroes its row counter after read and resets g_ovf_n via a fenced ticket,
// so no init kernel is needed across graph replays.

#define FEAT_D 128
#define E_MAX  1600000
#define N_MAX  50048
#define SLOT_CAP 64
#define OVF_MAX 65536
#define CONV_BLOCKS 288
#define BUILD_BLOCKS 1184

__device__ int g_idx_is64;
__device__ int g_idx_checked;
__device__ int g_counts[N_MAX];              // zero-init at module load; spmm re-zeroes
__device__ unsigned long long g_slots[(size_t)N_MAX * SLOT_CAP];
__device__ int g_ovf_n;
__device__ int g_ovf_row[OVF_MAX];
__device__ unsigned long long g_ovf_cv[OVF_MAX];
__device__ int g_done;                       // spmm completion ticket
__device__ __half2 g_bh[(size_t)N_MAX * (FEAT_D / 2)];

// ---------- pass 1 (fused): dtype detect + b->fp16 convert || bucket scatter ----------
__device__ __forceinline__ void place_edge(int r, unsigned int c, unsigned int vb) {
    unsigned long long cv = ((unsigned long long)vb << 32) | (unsigned long long)c;
    int pos = atomicAdd(&g_counts[r], 1);
    if (pos < SLOT_CAP) {
        g_slots[(size_t)r * SLOT_CAP + pos] = cv;
    } else {
        int op = atomicAdd(&g_ovf_n, 1);
        if (op < OVF_MAX) { g_ovf_row[op] = r; g_ovf_cv[op] = cv; }
    }
}

__device__ __forceinline__ int detect_is64(const int* idx32) {
    int zeros = 0;
    #pragma unroll
    for (int i = 0; i < 32; i++)
        if (__ldg(idx32 + 2 * i + 1) == 0) zeros++;
    return (zeros >= 24) ? 1 : 0;
}

__global__ void build_kernel(const void* __restrict__ indices,
                             const float* __restrict__ vals,
                             const float* __restrict__ b, int E, int n) {
    if (blockIdx.x < CONV_BLOCKS) {
        // --- convert b (f32) -> g_bh (fp16) ---
        int items = n * (FEAT_D / 4);
        int t = blockIdx.x * blockDim.x + threadIdx.x;
        int stride = CONV_BLOCKS * blockDim.x;
        const float4* b4 = reinterpret_cast<const float4*>(b);
        for (int i = t; i < items; i += stride) {
            float4 f = __ldg(b4 + i);
            g_bh[2 * (size_t)i]     = __floats2half2_rn(f.x, f.y);
            g_bh[2 * (size_t)i + 1] = __floats2half2_rn(f.z, f.w);
        }
        return;
    }

    // --- scatter edges into per-row buckets (dtype decided per-block; all
    //     blocks compute the same value deterministically from the data) ---
    int is64 = detect_is64((const int*)indices);
    int t = (blockIdx.x - CONV_BLOCKS) * blockDim.x + threadIdx.x;
    int stride = (BUILD_BLOCKS - CONV_BLOCKS) * blockDim.x;

    if (!is64) {
        const int* idx = (const int*)indices;
        int groups = E >> 2;
        const int4*   rows4 = reinterpret_cast<const int4*>(idx);
        const int4*   cols4 = reinterpret_cast<const int4*>(idx + E);
        const float4* vals4 = reinterpret_cast<const float4*>(vals);
        for (int g = t; g < groups; g += stride) {
            int4   r = __ldg(rows4 + g);
            int4   c = __ldg(cols4 + g);
            float4 v = __ldg(vals4 + g);
            place_edge(r.x, (unsigned)c.x, __float_as_uint(v.x));
            place_edge(r.y, (unsigned)c.y, __float_as_uint(v.y));
            place_edge(r.z, (unsigned)c.z, __float_as_uint(v.z));
            place_edge(r.w, (unsigned)c.w, __float_as_uint(v.w));
        }
        if (t < (E & 3)) {
            int e = (groups << 2) + t;
            place_edge(__ldg(idx + e), (unsigned)__ldg(idx + E + e),
                       __float_as_uint(__ldg(vals + e)));
        }
    } else {
        const long long* idx = (const long long*)indices;
        for (int i = t; i < E; i += stride)
            place_edge((int)__ldg(idx + i), (unsigned)__ldg(idx + E + i),
                       __float_as_uint(__ldg(vals + i)));
    }
}

// ---------- pass 2: warp-per-row SpMM + inline overflow + self-clean ----------
__global__ void __launch_bounds__(256) spmm_bucket_kernel(
    float* __restrict__ out, int n)
{
    const int lane = threadIdx.x & 31;
    int row = blockIdx.x * 8 + (threadIdx.x >> 5);

    if (row < n) {
        int deg = g_counts[row];
        if (lane == 0) g_counts[row] = 0;        // self-clean for next replay
        bool has_ovf = (deg > SLOT_CAP);
        if (deg > SLOT_CAP) deg = SLOT_CAP;
        const unsigned long long* __restrict__ slot =
            g_slots + (size_t)row * SLOT_CAP;

        const uint2* __restrict__ bh2 = reinterpret_cast<const uint2*>(g_bh);
        float ax = 0.f, ay = 0.f, az = 0.f, aw = 0.f;

        for (int base = 0; base < deg; base += 32) {
            int cnt = min(32, deg - base);
            unsigned long long cv = (lane < cnt) ? __ldg(slot + base + lane) : 0ull;
            int j = 0;
            for (; j + 8 <= cnt; j += 8) {
                unsigned long long ee[8];
                uint2 uu[8];
                #pragma unroll
                for (int k = 0; k < 8; k++)
                    ee[k] = __shfl_sync(0xffffffffu, cv, j + k);
                #pragma unroll
                for (int k = 0; k < 8; k++)
                    uu[k] = __ldg(bh2 + (size_t)(unsigned)ee[k] * 32 + lane);
                #pragma unroll
                for (int k = 0; k < 8; k++) {
                    float v = __uint_as_float((unsigned)(ee[k] >> 32));
                    float2 lo = __half22float2(*reinterpret_cast<__half2*>(&uu[k].x));
                    float2 hi = __half22float2(*reinterpret_cast<__half2*>(&uu[k].y));
                    ax += v * lo.x; ay += v * lo.y; az += v * hi.x; aw += v * hi.y;
                }
            }
            for (; j < cnt; j++) {
                unsigned long long e0 = __shfl_sync(0xffffffffu, cv, j);
                uint2 u0 = __ldg(bh2 + (size_t)(unsigned)e0 * 32 + lane);
                float v0 = __uint_as_float((unsigned)(e0 >> 32));
                float2 lo = __half22float2(*reinterpret_cast<__half2*>(&u0.x));
                float2 hi = __half22float2(*reinterpret_cast<__half2*>(&u0.y));
                ax += v0 * lo.x; ay += v0 * lo.y; az += v0 * hi.x; aw += v0 * hi.y;
            }
        }

        if (has_ovf) {
            int nov = min(g_ovf_n, OVF_MAX);
            for (int i = 0; i < nov; i++) {
                if (g_ovf_row[i] != row) continue;
                unsigned long long e0 = g_ovf_cv[i];
                uint2 u0 = __ldg(bh2 + (size_t)(unsigned)e0 * 32 + lane);
                float v0 = __uint_as_float((unsigned)(e0 >> 32));
                float2 lo = __half22float2(*reinterpret_cast<__half2*>(&u0.x));
                float2 hi = __half22float2(*reinterpret_cast<__half2*>(&u0.y));
                ax += v0 * lo.x; ay += v0 * lo.y; az += v0 * hi.x; aw += v0 * hi.y;
            }
        }

        reinterpret_cast<float4*>(out)[(long long)row * (FEAT_D / 4) + lane] =
            make_float4(ax, ay, az, aw);
    }

    // Last block to finish resets g_ovf_n (ticket is after all reads of it).
    __syncthreads();
    if (threadIdx.x == 0) {
        __threadfence();
        int d = atomicAdd(&g_done, 1);
        if (d == (int)gridDim.x - 1) {
            g_ovf_n = 0;
            g_done = 0;
        }
    }
}

// ---------- fallback: COO atomic path (full f32) ----------
__global__ void fb_init_kernel(const int* __restrict__ idx32) {
    g_idx_is64 = detect_is64(idx32);
}
__global__ void zero_out_kernel(float4* __restrict__ out, long long n4) {
    long long i = blockIdx.x * (long long)blockDim.x + threadIdx.x;
    long long stride = (long long)gridDim.x * blockDim.x;
    float4 z = make_float4(0.f, 0.f, 0.f, 0.f);
    for (; i < n4; i += stride) out[i] = z;
}
__global__ void __launch_bounds__(256) spmm_coo_kernel(
    const void* __restrict__ indices, const float* __restrict__ vals,
    const float* __restrict__ b, float* __restrict__ out, int E)
{
    int warp = (int)((blockIdx.x * (long long)blockDim.x + threadIdx.x) >> 5);
    int lane = threadIdx.x & 31;
    if (warp >= E) return;
    int r, c;
    if (g_idx_is64) {
        r = (int)__ldg((const long long*)indices + warp);
        c = (int)__ldg((const long long*)indices + E + warp);
    } else {
        r = __ldg((const int*)indices + warp);
        c = __ldg((const int*)indices + E + warp);
    }
    float v = __ldg(vals + warp);
    const float4* brow = reinterpret_cast<const float4*>(b) + (long long)c * (FEAT_D / 4);
    float4 bv = __ldg(brow + lane);
    float* dst = out + (long long)r * FEAT_D + lane * 4;
    asm volatile("red.global.add.v4.f32 [%0], {%1, %2, %3, %4};"
                 :: "l"(dst), "f"(bv.x * v), "f"(bv.y * v),
                    "f"(bv.z * v), "f"(bv.w * v) : "memory");
}

extern "C" void kernel_launch(void* const* d_in, const int* in_sizes, int n_in,
                              void* d_out, int out_size)
{
    const void*  indices = d_in[0];
    const float* vals    = (const float*)d_in[1];
    const float* b       = (const float*)d_in[n_in - 1];

    int E = in_sizes[1];
    int n = out_size / FEAT_D;
    float* out = (float*)d_out;

    bool ok = (E <= E_MAX) && (n <= N_MAX) && ((long long)E <= (long long)n * 40);

    if (ok) {
        build_kernel<<<BUILD_BLOCKS, 256>>>(indices, vals, b, E, n);
        int blocks = (n + 7) / 8;
        spmm_bucket_kernel<<<blocks, 256>>>(out, n);
    } else {
        fb_init_kernel<<<1, 32>>>((const int*)indices);
        zero_out_kernel<<<1184, 256>>>(reinterpret_cast<float4*>(out),
                                       (long long)out_size / 4);
        long long total_threads = (long long)E * 32;
        long long blocks = (total_threads + 255) / 256;
        spmm_coo_kernel<<<(unsigned int)blocks, 256>>>(indices, vals, b, out, E);
    }
}

// round 9
// speedup vs baseline: 1.0205x; 1.0205x over previous
#include <cuda_runtime.h>
#include <cuda_fp16.h>
#include <cstdint>

// COO SpMM: out[row[e], :] += values[e] * b[col[e], :]
// indices: [2, E] int32 or int64 (runtime-detected); values: f32 [E];
// b: f32 [N, 128]; out: f32 [N, 128].
//
// R9: two kernels. build = (b->fp16 convert || bucket scatter, split blocks).
// spmm = warp-per-row, R6's proven 4-wide gather batch (8-wide spilled to
// local in R8 — reverted), inline overflow, self-cleaning counters/ticket.

#define FEAT_D 128
#define E_MAX  1600000
#define N_MAX  50048
#define SLOT_CAP 64
#define OVF_MAX 65536
#define CONV_BLOCKS 288
#define BUILD_BLOCKS 1184

__device__ int g_idx_is64;
__device__ int g_counts[N_MAX];              // zero at module load; spmm re-zeroes
__device__ unsigned long long g_slots[(size_t)N_MAX * SLOT_CAP];
__device__ int g_ovf_n;
__device__ int g_ovf_row[OVF_MAX];
__device__ unsigned long long g_ovf_cv[OVF_MAX];
__device__ int g_done;
__device__ __half2 g_bh[(size_t)N_MAX * (FEAT_D / 2)];

__device__ __forceinline__ void place_edge(int r, unsigned int c, unsigned int vb) {
    unsigned long long cv = ((unsigned long long)vb << 32) | (unsigned long long)c;
    int pos = atomicAdd(&g_counts[r], 1);
    if (pos < SLOT_CAP) {
        g_slots[(size_t)r * SLOT_CAP + pos] = cv;
    } else {
        int op = atomicAdd(&g_ovf_n, 1);
        if (op < OVF_MAX) { g_ovf_row[op] = r; g_ovf_cv[op] = cv; }
    }
}

__device__ __forceinline__ int detect_is64(const int* idx32) {
    int zeros = 0;
    #pragma unroll
    for (int i = 0; i < 32; i++)
        if (__ldg(idx32 + 2 * i + 1) == 0) zeros++;
    return (zeros >= 24) ? 1 : 0;
}

// ---------- pass 1 (fused): b->fp16 convert || bucket scatter ----------
__global__ void build_kernel(const void* __restrict__ indices,
                             const float* __restrict__ vals,
                             const float* __restrict__ b, int E, int n) {
    if (blockIdx.x < CONV_BLOCKS) {
        int items = n * (FEAT_D / 4);
        int t = blockIdx.x * blockDim.x + threadIdx.x;
        int stride = CONV_BLOCKS * blockDim.x;
        const float4* b4 = reinterpret_cast<const float4*>(b);
        for (int i = t; i < items; i += stride) {
            float4 f = __ldg(b4 + i);
            g_bh[2 * (size_t)i]     = __floats2half2_rn(f.x, f.y);
            g_bh[2 * (size_t)i + 1] = __floats2half2_rn(f.z, f.w);
        }
        return;
    }

    int is64 = detect_is64((const int*)indices);
    int t = (blockIdx.x - CONV_BLOCKS) * blockDim.x + threadIdx.x;
    int stride = (BUILD_BLOCKS - CONV_BLOCKS) * blockDim.x;

    if (!is64) {
        const int* idx = (const int*)indices;
        int groups = E >> 2;
        const int4*   rows4 = reinterpret_cast<const int4*>(idx);
        const int4*   cols4 = reinterpret_cast<const int4*>(idx + E);
        const float4* vals4 = reinterpret_cast<const float4*>(vals);
        for (int g = t; g < groups; g += stride) {
            int4   r = __ldg(rows4 + g);
            int4   c = __ldg(cols4 + g);
            float4 v = __ldg(vals4 + g);
            place_edge(r.x, (unsigned)c.x, __float_as_uint(v.x));
            place_edge(r.y, (unsigned)c.y, __float_as_uint(v.y));
            place_edge(r.z, (unsigned)c.z, __float_as_uint(v.z));
            place_edge(r.w, (unsigned)c.w, __float_as_uint(v.w));
        }
        if (t < (E & 3)) {
            int e = (groups << 2) + t;
            place_edge(__ldg(idx + e), (unsigned)__ldg(idx + E + e),
                       __float_as_uint(__ldg(vals + e)));
        }
    } else {
        const long long* idx = (const long long*)indices;
        for (int i = t; i < E; i += stride)
            place_edge((int)__ldg(idx + i), (unsigned)__ldg(idx + E + i),
                       __float_as_uint(__ldg(vals + i)));
    }
}

// ---------- pass 2: warp-per-row SpMM (R6 4-wide) + inline ovf + self-clean ----------
__global__ void __launch_bounds__(256) spmm_bucket_kernel(
    float* __restrict__ out, int n)
{
    const int lane = threadIdx.x & 31;
    int row = blockIdx.x * 8 + (threadIdx.x >> 5);

    if (row < n) {
        int deg = g_counts[row];
        if (lane == 0) g_counts[row] = 0;      // self-clean for next replay
        bool has_ovf = (deg > SLOT_CAP);
        if (deg > SLOT_CAP) deg = SLOT_CAP;
        const unsigned long long* __restrict__ slot =
            g_slots + (size_t)row * SLOT_CAP;

        const uint2* __restrict__ bh2 = reinterpret_cast<const uint2*>(g_bh);
        float ax = 0.f, ay = 0.f, az = 0.f, aw = 0.f;

        for (int base = 0; base < deg; base += 32) {
            int cnt = min(32, deg - base);
            unsigned long long cv = (lane < cnt) ? __ldg(slot + base + lane) : 0ull;
            int j = 0;
            for (; j + 4 <= cnt; j += 4) {
                unsigned long long e0 = __shfl_sync(0xffffffffu, cv, j);
                unsigned long long e1 = __shfl_sync(0xffffffffu, cv, j + 1);
                unsigned long long e2 = __shfl_sync(0xffffffffu, cv, j + 2);
                unsigned long long e3 = __shfl_sync(0xffffffffu, cv, j + 3);
                uint2 u0 = __ldg(bh2 + (size_t)(unsigned)e0 * 32 + lane);
                uint2 u1 = __ldg(bh2 + (size_t)(unsigned)e1 * 32 + lane);
                uint2 u2 = __ldg(bh2 + (size_t)(unsigned)e2 * 32 + lane);
                uint2 u3 = __ldg(bh2 + (size_t)(unsigned)e3 * 32 + lane);
                float v0 = __uint_as_float((unsigned)(e0 >> 32));
                float v1 = __uint_as_float((unsigned)(e1 >> 32));
                float v2 = __uint_as_float((unsigned)(e2 >> 32));
                float v3 = __uint_as_float((unsigned)(e3 >> 32));
                float2 a0 = __half22float2(*reinterpret_cast<__half2*>(&u0.x));
                float2 b0 = __half22float2(*reinterpret_cast<__half2*>(&u0.y));
                float2 a1 = __half22float2(*reinterpret_cast<__half2*>(&u1.x));
                float2 b1 = __half22float2(*reinterpret_cast<__half2*>(&u1.y));
                float2 a2 = __half22float2(*reinterpret_cast<__half2*>(&u2.x));
                float2 b2 = __half22float2(*reinterpret_cast<__half2*>(&u2.y));
                float2 a3 = __half22float2(*reinterpret_cast<__half2*>(&u3.x));
                float2 b3 = __half22float2(*reinterpret_cast<__half2*>(&u3.y));
                ax += v0 * a0.x + v1 * a1.x + v2 * a2.x + v3 * a3.x;
                ay += v0 * a0.y + v1 * a1.y + v2 * a2.y + v3 * a3.y;
                az += v0 * b0.x + v1 * b1.x + v2 * b2.x + v3 * b3.x;
                aw += v0 * b0.y + v1 * b1.y + v2 * b2.y + v3 * b3.y;
            }
            for (; j < cnt; j++) {
                unsigned long long e0 = __shfl_sync(0xffffffffu, cv, j);
                uint2 u0 = __ldg(bh2 + (size_t)(unsigned)e0 * 32 + lane);
                float v0 = __uint_as_float((unsigned)(e0 >> 32));
                float2 a0 = __half22float2(*reinterpret_cast<__half2*>(&u0.x));
                float2 b0 = __half22float2(*reinterpret_cast<__half2*>(&u0.y));
                ax += v0 * a0.x; ay += v0 * a0.y; az += v0 * b0.x; aw += v0 * b0.y;
            }
        }

        if (has_ovf) {
            int nov = min(g_ovf_n, OVF_MAX);
            for (int i = 0; i < nov; i++) {
                if (g_ovf_row[i] != row) continue;
                unsigned long long e0 = g_ovf_cv[i];
                uint2 u0 = __ldg(bh2 + (size_t)(unsigned)e0 * 32 + lane);
                float v0 = __uint_as_float((unsigned)(e0 >> 32));
                float2 a0 = __half22float2(*reinterpret_cast<__half2*>(&u0.x));
                float2 b0 = __half22float2(*reinterpret_cast<__half2*>(&u0.y));
                ax += v0 * a0.x; ay += v0 * a0.y; az += v0 * b0.x; aw += v0 * b0.y;
            }
        }

        reinterpret_cast<float4*>(out)[(long long)row * (FEAT_D / 4) + lane] =
            make_float4(ax, ay, az, aw);
    }

    __syncthreads();
    if (threadIdx.x == 0) {
        __threadfence();
        int d = atomicAdd(&g_done, 1);
        if (d == (int)gridDim.x - 1) {
            g_ovf_n = 0;
            g_done = 0;
        }
    }
}

// ---------- fallback: COO atomic path (full f32) ----------
__global__ void fb_init_kernel(const int* __restrict__ idx32) {
    g_idx_is64 = detect_is64(idx32);
}
__global__ void zero_out_kernel(float4* __restrict__ out, long long n4) {
    long long i = blockIdx.x * (long long)blockDim.x + threadIdx.x;
    long long stride = (long long)gridDim.x * blockDim.x;
    float4 z = make_float4(0.f, 0.f, 0.f, 0.f);
    for (; i < n4; i += stride) out[i] = z;
}
__global__ void __launch_bounds__(256) spmm_coo_kernel(
    const void* __restrict__ indices, const float* __restrict__ vals,
    const float* __restrict__ b, float* __restrict__ out, int E)
{
    int warp = (int)((blockIdx.x * (long long)blockDim.x + threadIdx.x) >> 5);
    int lane = threadIdx.x & 31;
    if (warp >= E) return;
    int r, c;
    if (g_idx_is64) {
        r = (int)__ldg((const long long*)indices + warp);
        c = (int)__ldg((const long long*)indices + E + warp);
    } else {
        r = __ldg((const int*)indices + warp);
        c = __ldg((const int*)indices + E + warp);
    }
    float v = __ldg(vals + warp);
    const float4* brow = reinterpret_cast<const float4*>(b) + (long long)c * (FEAT_D / 4);
    float4 bv = __ldg(brow + lane);
    float* dst = out + (long long)r * FEAT_D + lane * 4;
    asm volatile("red.global.add.v4.f32 [%0], {%1, %2, %3, %4};"
                 :: "l"(dst), "f"(bv.x * v), "f"(bv.y * v),
                    "f"(bv.z * v), "f"(bv.w * v) : "memory");
}

extern "C" void kernel_launch(void* const* d_in, const int* in_sizes, int n_in,
                              void* d_out, int out_size)
{
    const void*  indices = d_in[0];
    const float* vals    = (const float*)d_in[1];
    const float* b       = (const float*)d_in[n_in - 1];

    int E = in_sizes[1];
    int n = out_size / FEAT_D;
    float* out = (float*)d_out;

    bool ok = (E <= E_MAX) && (n <= N_MAX) && ((long long)E <= (long long)n * 40);

    if (ok) {
        build_kernel<<<BUILD_BLOCKS, 256>>>(indices, vals, b, E, n);
        int blocks = (n + 7) / 8;
        spmm_bucket_kernel<<<blocks, 256>>>(out, n);
    } else {
        fb_init_kernel<<<1, 32>>>((const int*)indices);
        zero_out_kernel<<<1184, 256>>>(reinterpret_cast<float4*>(out),
                                       (long long)out_size / 4);
        long long total_threads = (long long)E * 32;
        long long blocks = (total_threads + 255) / 256;
        spmm_coo_kernel<<<(unsigned int)blocks, 256>>>(indices, vals, b, out, E);
    }
}

// round 10
// speedup vs baseline: 1.0281x; 1.0074x over previous
#include <cuda_runtime.h>
#include <cuda_fp16.h>
#include <cstdint>

// COO SpMM: out[row[e], :] += values[e] * b[col[e], :]
// indices: [2, E] int32 or int64 (runtime-detected); values: f32 [E];
// b: f32 [N, 128]; out: f32 [N, 128].
//
// R9: two kernels. build = (b->fp16 convert || bucket scatter, split blocks).
// spmm = warp-per-row, R6's proven 4-wide gather batch (8-wide spilled to
// local in R8 — reverted), inline overflow, self-cleaning counters/ticket.

#define FEAT_D 128
#define E_MAX  1600000
#define N_MAX  50048
#define SLOT_CAP 64
#define OVF_MAX 65536
#define CONV_BLOCKS 288
#define BUILD_BLOCKS 1184

__device__ int g_idx_is64;
__device__ int g_counts[N_MAX];              // zero at module load; spmm re-zeroes
__device__ unsigned long long g_slots[(size_t)N_MAX * SLOT_CAP];
__device__ int g_ovf_n;
__device__ int g_ovf_row[OVF_MAX];
__device__ unsigned long long g_ovf_cv[OVF_MAX];
__device__ int g_done;
__device__ __half2 g_bh[(size_t)N_MAX * (FEAT_D / 2)];

__device__ __forceinline__ void place_edge(int r, unsigned int c, unsigned int vb) {
    unsigned long long cv = ((unsigned long long)vb << 32) | (unsigned long long)c;
    int pos = atomicAdd(&g_counts[r], 1);
    if (pos < SLOT_CAP) {
        g_slots[(size_t)r * SLOT_CAP + pos] = cv;
    } else {
        int op = atomicAdd(&g_ovf_n, 1);
        if (op < OVF_MAX) { g_ovf_row[op] = r; g_ovf_cv[op] = cv; }
    }
}

__device__ __forceinline__ int detect_is64(const int* idx32) {
    int zeros = 0;
    #pragma unroll
    for (int i = 0; i < 32; i++)
        if (__ldg(idx32 + 2 * i + 1) == 0) zeros++;
    return (zeros >= 24) ? 1 : 0;
}

// ---------- pass 1 (fused): b->fp16 convert || bucket scatter ----------
__global__ void build_kernel(const void* __restrict__ indices,
                             const float* __restrict__ vals,
                             const float* __restrict__ b, int E, int n) {
    if (blockIdx.x < CONV_BLOCKS) {
        int items = n * (FEAT_D / 4);
        int t = blockIdx.x * blockDim.x + threadIdx.x;
        int stride = CONV_BLOCKS * blockDim.x;
        const float4* b4 = reinterpret_cast<const float4*>(b);
        for (int i = t; i < items; i += stride) {
            float4 f = __ldg(b4 + i);
            g_bh[2 * (size_t)i]     = __floats2half2_rn(f.x, f.y);
            g_bh[2 * (size_t)i + 1] = __floats2half2_rn(f.z, f.w);
        }
        return;
    }

    int is64 = detect_is64((const int*)indices);
    int t = (blockIdx.x - CONV_BLOCKS) * blockDim.x + threadIdx.x;
    int stride = (BUILD_BLOCKS - CONV_BLOCKS) * blockDim.x;

    if (!is64) {
        const int* idx = (const int*)indices;
        int groups = E >> 2;
        const int4*   rows4 = reinterpret_cast<const int4*>(idx);
        const int4*   cols4 = reinterpret_cast<const int4*>(idx + E);
        const float4* vals4 = reinterpret_cast<const float4*>(vals);
        for (int g = t; g < groups; g += stride) {
            int4   r = __ldg(rows4 + g);
            int4   c = __ldg(cols4 + g);
            float4 v = __ldg(vals4 + g);
            place_edge(r.x, (unsigned)c.x, __float_as_uint(v.x));
            place_edge(r.y, (unsigned)c.y, __float_as_uint(v.y));
            place_edge(r.z, (unsigned)c.z, __float_as_uint(v.z));
            place_edge(r.w, (unsigned)c.w, __float_as_uint(v.w));
        }
        if (t < (E & 3)) {
            int e = (groups << 2) + t;
            place_edge(__ldg(idx + e), (unsigned)__ldg(idx + E + e),
                       __float_as_uint(__ldg(vals + e)));
        }
    } else {
        const long long* idx = (const long long*)indices;
        for (int i = t; i < E; i += stride)
            place_edge((int)__ldg(idx + i), (unsigned)__ldg(idx + E + i),
                       __float_as_uint(__ldg(vals + i)));
    }
}

// ---------- pass 2: warp-per-row SpMM (R6 4-wide) + inline ovf + self-clean ----------
__global__ void __launch_bounds__(256) spmm_bucket_kernel(
    float* __restrict__ out, int n)
{
    const int lane = threadIdx.x & 31;
    int row = blockIdx.x * 8 + (threadIdx.x >> 5);

    if (row < n) {
        int deg = g_counts[row];
        if (lane == 0) g_counts[row] = 0;      // self-clean for next replay
        bool has_ovf = (deg > SLOT_CAP);
        if (deg > SLOT_CAP) deg = SLOT_CAP;
        const unsigned long long* __restrict__ slot =
            g_slots + (size_t)row * SLOT_CAP;

        const uint2* __restrict__ bh2 = reinterpret_cast<const uint2*>(g_bh);
        float ax = 0.f, ay = 0.f, az = 0.f, aw = 0.f;

        for (int base = 0; base < deg; base += 32) {
            int cnt = min(32, deg - base);
            unsigned long long cv = (lane < cnt) ? __ldg(slot + base + lane) : 0ull;
            int j = 0;
            for (; j + 4 <= cnt; j += 4) {
                unsigned long long e0 = __shfl_sync(0xffffffffu, cv, j);
                unsigned long long e1 = __shfl_sync(0xffffffffu, cv, j + 1);
                unsigned long long e2 = __shfl_sync(0xffffffffu, cv, j + 2);
                unsigned long long e3 = __shfl_sync(0xffffffffu, cv, j + 3);
                uint2 u0 = __ldg(bh2 + (size_t)(unsigned)e0 * 32 + lane);
                uint2 u1 = __ldg(bh2 + (size_t)(unsigned)e1 * 32 + lane);
                uint2 u2 = __ldg(bh2 + (size_t)(unsigned)e2 * 32 + lane);
                uint2 u3 = __ldg(bh2 + (size_t)(unsigned)e3 * 32 + lane);
                float v0 = __uint_as_float((unsigned)(e0 >> 32));
                float v1 = __uint_as_float((unsigned)(e1 >> 32));
                float v2 = __uint_as_float((unsigned)(e2 >> 32));
                float v3 = __uint_as_float((unsigned)(e3 >> 32));
                float2 a0 = __half22float2(*reinterpret_cast<__half2*>(&u0.x));
                float2 b0 = __half22float2(*reinterpret_cast<__half2*>(&u0.y));
                float2 a1 = __half22float2(*reinterpret_cast<__half2*>(&u1.x));
                float2 b1 = __half22float2(*reinterpret_cast<__half2*>(&u1.y));
                float2 a2 = __half22float2(*reinterpret_cast<__half2*>(&u2.x));
                float2 b2 = __half22float2(*reinterpret_cast<__half2*>(&u2.y));
                float2 a3 = __half22float2(*reinterpret_cast<__half2*>(&u3.x));
                float2 b3 = __half22float2(*reinterpret_cast<__half2*>(&u3.y));
                ax += v0 * a0.x + v1 * a1.x + v2 * a2.x + v3 * a3.x;
                ay += v0 * a0.y + v1 * a1.y + v2 * a2.y + v3 * a3.y;
                az += v0 * b0.x + v1 * b1.x + v2 * b2.x + v3 * b3.x;
                aw += v0 * b0.y + v1 * b1.y + v2 * b2.y + v3 * b3.y;
            }
            for (; j < cnt; j++) {
                unsigned long long e0 = __shfl_sync(0xffffffffu, cv, j);
                uint2 u0 = __ldg(bh2 + (size_t)(unsigned)e0 * 32 + lane);
                float v0 = __uint_as_float((unsigned)(e0 >> 32));
                float2 a0 = __half22float2(*reinterpret_cast<__half2*>(&u0.x));
                float2 b0 = __half22float2(*reinterpret_cast<__half2*>(&u0.y));
                ax += v0 * a0.x; ay += v0 * a0.y; az += v0 * b0.x; aw += v0 * b0.y;
            }
        }

        if (has_ovf) {
            int nov = min(g_ovf_n, OVF_MAX);
            for (int i = 0; i < nov; i++) {
                if (g_ovf_row[i] != row) continue;
                unsigned long long e0 = g_ovf_cv[i];
                uint2 u0 = __ldg(bh2 + (size_t)(unsigned)e0 * 32 + lane);
                float v0 = __uint_as_float((unsigned)(e0 >> 32));
                float2 a0 = __half22float2(*reinterpret_cast<__half2*>(&u0.x));
                float2 b0 = __half22float2(*reinterpret_cast<__half2*>(&u0.y));
                ax += v0 * a0.x; ay += v0 * a0.y; az += v0 * b0.x; aw += v0 * b0.y;
            }
        }

        reinterpret_cast<float4*>(out)[(long long)row * (FEAT_D / 4) + lane] =
            make_float4(ax, ay, az, aw);
    }

    __syncthreads();
    if (threadIdx.x == 0) {
        __threadfence();
        int d = atomicAdd(&g_done, 1);
        if (d == (int)gridDim.x - 1) {
            g_ovf_n = 0;
            g_done = 0;
        }
    }
}

// ---------- fallback: COO atomic path (full f32) ----------
__global__ void fb_init_kernel(const int* __restrict__ idx32) {
    g_idx_is64 = detect_is64(idx32);
}
__global__ void zero_out_kernel(float4* __restrict__ out, long long n4) {
    long long i = blockIdx.x * (long long)blockDim.x + threadIdx.x;
    long long stride = (long long)gridDim.x * blockDim.x;
    float4 z = make_float4(0.f, 0.f, 0.f, 0.f);
    for (; i < n4; i += stride) out[i] = z;
}
__global__ void __launch_bounds__(256) spmm_coo_kernel(
    const void* __restrict__ indices, const float* __restrict__ vals,
    const float* __restrict__ b, float* __restrict__ out, int E)
{
    int warp = (int)((blockIdx.x * (long long)blockDim.x + threadIdx.x) >> 5);
    int lane = threadIdx.x & 31;
    if (warp >= E) return;
    int r, c;
    if (g_idx_is64) {
        r = (int)__ldg((const long long*)indices + warp);
        c = (int)__ldg((const long long*)indices + E + warp);
    } else {
        r = __ldg((const int*)indices + warp);
        c = __ldg((const int*)indices + E + warp);
    }
    float v = __ldg(vals + warp);
    const float4* brow = reinterpret_cast<const float4*>(b) + (long long)c * (FEAT_D / 4);
    float4 bv = __ldg(brow + lane);
    float* dst = out + (long long)r * FEAT_D + lane * 4;
    asm volatile("red.global.add.v4.f32 [%0], {%1, %2, %3, %4};"
                 :: "l"(dst), "f"(bv.x * v), "f"(bv.y * v),
                    "f"(bv.z * v), "f"(bv.w * v) : "memory");
}

extern "C" void kernel_launch(void* const* d_in, const int* in_sizes, int n_in,
                              void* d_out, int out_size)
{
    const void*  indices = d_in[0];
    const float* vals    = (const float*)d_in[1];
    const float* b       = (const float*)d_in[n_in - 1];

    int E = in_sizes[1];
    int n = out_size / FEAT_D;
    float* out = (float*)d_out;

    bool ok = (E <= E_MAX) && (n <= N_MAX) && ((long long)E <= (long long)n * 40);

    if (ok) {
        build_kernel<<<BUILD_BLOCKS, 256>>>(indices, vals, b, E, n);
        int blocks = (n + 7) / 8;
        spmm_bucket_kernel<<<blocks, 256>>>(out, n);
    } else {
        fb_init_kernel<<<1, 32>>>((const int*)indices);
        zero_out_kernel<<<1184, 256>>>(reinterpret_cast<float4*>(out),
                                       (long long)out_size / 4);
        long long total_threads = (long long)E * 32;
        long long blocks = (total_threads + 255) / 256;
        spmm_coo_kernel<<<(unsigned int)blocks, 256>>>(indices, vals, b, out, E);
    }
}

// round 11
// speedup vs baseline: 2.0291x; 1.9737x over previous
#include <cuda_runtime.h>
#include <cuda_fp16.h>
#include <cstdint>

// COO SpMM: out[row[e], :] += values[e] * b[col[e], :]
// indices: [2, E] int32 or int64 (runtime-detected); values: f32 [E];
// b: f32 [N, 128]; out: f32 [N, 128].
//
// R11 = exact revert to the verified R6 champion (77.9us):
// init (dtype flag + zero counters) -> build (b->fp16 convert || bucket
// scatter, split blocks) -> spmm (warp-per-row, 4-wide gather batch, one
// store per row) -> ovf patch-up kernel. No barriers/tickets/self-clean.

#define FEAT_D 128
#define E_MAX  1600000
#define N_MAX  50048
#define SLOT_CAP 64
#define OVF_MAX 65536
#define CONV_BLOCKS 288
#define BUILD_BLOCKS 1184

__device__ int g_idx_is64;
__device__ int g_counts[N_MAX];
__device__ unsigned long long g_slots[(size_t)N_MAX * SLOT_CAP]; // hi=val bits, lo=col
__device__ int g_ovf_n;
__device__ int g_ovf_row[OVF_MAX];
__device__ unsigned long long g_ovf_cv[OVF_MAX];
__device__ __half2 g_bh[(size_t)N_MAX * (FEAT_D / 2)];  // b in fp16

__device__ __forceinline__ int load_row(const void* idx, int e, int E) {
    if (g_idx_is64) return (int)__ldg((const long long*)idx + e);
    return __ldg((const int*)idx + e);
}
__device__ __forceinline__ int load_col(const void* idx, int e, int E) {
    if (g_idx_is64) return (int)__ldg((const long long*)idx + E + e);
    return __ldg((const int*)idx + E + e);
}

// ---------- pass 0: detect dtype + zero counters ----------
__global__ void init_kernel(const int* __restrict__ idx32, int n) {
    if (blockIdx.x == 0 && threadIdx.x == 0) {
        int zeros = 0;
        #pragma unroll
        for (int i = 0; i < 32; i++)
            if (idx32[2 * i + 1] == 0) zeros++;
        g_idx_is64 = (zeros >= 24) ? 1 : 0;
        g_ovf_n = 0;
    }
    int i = blockIdx.x * blockDim.x + threadIdx.x;
    int stride = gridDim.x * blockDim.x;
    for (; i < n; i += stride) g_counts[i] = 0;
}

// ---------- pass 1 (fused): b->fp16 convert || bucket scatter ----------
__device__ __forceinline__ void place_edge(int r, unsigned int c, unsigned int vb) {
    unsigned long long cv = ((unsigned long long)vb << 32) | (unsigned long long)c;
    int pos = atomicAdd(&g_counts[r], 1);
    if (pos < SLOT_CAP) {
        g_slots[(size_t)r * SLOT_CAP + pos] = cv;
    } else {
        int op = atomicAdd(&g_ovf_n, 1);
        if (op < OVF_MAX) { g_ovf_row[op] = r; g_ovf_cv[op] = cv; }
    }
}

__global__ void build_kernel(const void* __restrict__ indices,
                             const float* __restrict__ vals,
                             const float* __restrict__ b, int E, int n) {
    if (blockIdx.x < CONV_BLOCKS) {
        // --- convert b (f32) -> g_bh (fp16): thread handles 4 floats ---
        int items = n * (FEAT_D / 4);
        int t = blockIdx.x * blockDim.x + threadIdx.x;
        int stride = CONV_BLOCKS * blockDim.x;
        const float4* b4 = reinterpret_cast<const float4*>(b);
        for (int i = t; i < items; i += stride) {
            float4 f = __ldg(b4 + i);
            g_bh[2 * (size_t)i]     = __floats2half2_rn(f.x, f.y);
            g_bh[2 * (size_t)i + 1] = __floats2half2_rn(f.z, f.w);
        }
        return;
    }

    // --- scatter edges into per-row buckets ---
    int t = (blockIdx.x - CONV_BLOCKS) * blockDim.x + threadIdx.x;
    int stride = (BUILD_BLOCKS - CONV_BLOCKS) * blockDim.x;

    if (!g_idx_is64) {
        const int* idx = (const int*)indices;
        int groups = E >> 2;
        const int4*   rows4 = reinterpret_cast<const int4*>(idx);
        const int4*   cols4 = reinterpret_cast<const int4*>(idx + E);
        const float4* vals4 = reinterpret_cast<const float4*>(vals);
        for (int g = t; g < groups; g += stride) {
            int4   r = __ldg(rows4 + g);
            int4   c = __ldg(cols4 + g);
            float4 v = __ldg(vals4 + g);
            place_edge(r.x, (unsigned)c.x, __float_as_uint(v.x));
            place_edge(r.y, (unsigned)c.y, __float_as_uint(v.y));
            place_edge(r.z, (unsigned)c.z, __float_as_uint(v.z));
            place_edge(r.w, (unsigned)c.w, __float_as_uint(v.w));
        }
        if (t < (E & 3)) {
            int e = (groups << 2) + t;
            place_edge(__ldg(idx + e), (unsigned)__ldg(idx + E + e),
                       __float_as_uint(__ldg(vals + e)));
        }
    } else {
        const long long* idx = (const long long*)indices;
        for (int i = t; i < E; i += stride)
            place_edge((int)__ldg(idx + i), (unsigned)__ldg(idx + E + i),
                       __float_as_uint(__ldg(vals + i)));
    }
}

// ---------- pass 2: warp-per-row SpMM (fp16 gather, f32 accumulate) ----------
__global__ void __launch_bounds__(256) spmm_bucket_kernel(
    float* __restrict__ out, int n)
{
    const int lane = threadIdx.x & 31;
    int row = blockIdx.x * 8 + (threadIdx.x >> 5);
    if (row >= n) return;

    int deg = g_counts[row];
    if (deg > SLOT_CAP) deg = SLOT_CAP;
    const unsigned long long* __restrict__ slot = g_slots + (size_t)row * SLOT_CAP;

    // Row c of b (fp16): 32 uint2 (8B per lane) = 256B per row.
    const uint2* __restrict__ bh2 = reinterpret_cast<const uint2*>(g_bh);
    float ax = 0.f, ay = 0.f, az = 0.f, aw = 0.f;

    for (int base = 0; base < deg; base += 32) {
        int cnt = min(32, deg - base);
        unsigned long long cv = (lane < cnt) ? __ldg(slot + base + lane) : 0ull;
        int j = 0;
        for (; j + 4 <= cnt; j += 4) {
            unsigned long long e0 = __shfl_sync(0xffffffffu, cv, j);
            unsigned long long e1 = __shfl_sync(0xffffffffu, cv, j + 1);
            unsigned long long e2 = __shfl_sync(0xffffffffu, cv, j + 2);
            unsigned long long e3 = __shfl_sync(0xffffffffu, cv, j + 3);
            uint2 u0 = __ldg(bh2 + (size_t)(unsigned)e0 * 32 + lane);
            uint2 u1 = __ldg(bh2 + (size_t)(unsigned)e1 * 32 + lane);
            uint2 u2 = __ldg(bh2 + (size_t)(unsigned)e2 * 32 + lane);
            uint2 u3 = __ldg(bh2 + (size_t)(unsigned)e3 * 32 + lane);
            float v0 = __uint_as_float((unsigned)(e0 >> 32));
            float v1 = __uint_as_float((unsigned)(e1 >> 32));
            float v2 = __uint_as_float((unsigned)(e2 >> 32));
            float v3 = __uint_as_float((unsigned)(e3 >> 32));
            float2 a0 = __half22float2(*reinterpret_cast<__half2*>(&u0.x));
            float2 b0 = __half22float2(*reinterpret_cast<__half2*>(&u0.y));
            float2 a1 = __half22float2(*reinterpret_cast<__half2*>(&u1.x));
            float2 b1 = __half22float2(*reinterpret_cast<__half2*>(&u1.y));
            float2 a2 = __half22float2(*reinterpret_cast<__half2*>(&u2.x));
            float2 b2 = __half22float2(*reinterpret_cast<__half2*>(&u2.y));
            float2 a3 = __half22float2(*reinterpret_cast<__half2*>(&u3.x));
            float2 b3 = __half22float2(*reinterpret_cast<__half2*>(&u3.y));
            ax += v0 * a0.x + v1 * a1.x + v2 * a2.x + v3 * a3.x;
            ay += v0 * a0.y + v1 * a1.y + v2 * a2.y + v3 * a3.y;
            az += v0 * b0.x + v1 * b1.x + v2 * b2.x + v3 * b3.x;
            aw += v0 * b0.y + v1 * b1.y + v2 * b2.y + v3 * b3.y;
        }
        for (; j < cnt; j++) {
            unsigned long long e0 = __shfl_sync(0xffffffffu, cv, j);
            uint2 u0 = __ldg(bh2 + (size_t)(unsigned)e0 * 32 + lane);
            float v0 = __uint_as_float((unsigned)(e0 >> 32));
            float2 a0 = __half22float2(*reinterpret_cast<__half2*>(&u0.x));
            float2 b0 = __half22float2(*reinterpret_cast<__half2*>(&u0.y));
            ax += v0 * a0.x; ay += v0 * a0.y; az += v0 * b0.x; aw += v0 * b0.y;
        }
    }

    reinterpret_cast<float4*>(out)[(long long)row * (FEAT_D / 4) + lane] =
        make_float4(ax, ay, az, aw);
}

// ---------- pass 3: patch overflow edges (f32 b, usually zero work) ----------
__global__ void ovf_kernel(const float* __restrict__ b, float* __restrict__ out) {
    int nov = min(g_ovf_n, OVF_MAX);
    int warp = (blockIdx.x * blockDim.x + threadIdx.x) >> 5;
    int nwarps = (gridDim.x * blockDim.x) >> 5;
    int lane = threadIdx.x & 31;
    for (int i = warp; i < nov; i += nwarps) {
        int r = g_ovf_row[i];
        unsigned long long cv = g_ovf_cv[i];
        float v = __uint_as_float((unsigned)(cv >> 32));
        const float4* brow =
            reinterpret_cast<const float4*>(b) + (long long)(unsigned)cv * (FEAT_D / 4);
        float4 bv = __ldg(brow + lane);
        float* dst = out + (long long)r * FEAT_D + lane * 4;
        asm volatile("red.global.add.v4.f32 [%0], {%1, %2, %3, %4};"
                     :: "l"(dst), "f"(bv.x * v), "f"(bv.y * v),
                        "f"(bv.z * v), "f"(bv.w * v) : "memory");
    }
}

// ---------- fallback: COO atomic path (full f32) ----------
__global__ void zero_out_kernel(float4* __restrict__ out, long long n4) {
    long long i = blockIdx.x * (long long)blockDim.x + threadIdx.x;
    long long stride = (long long)gridDim.x * blockDim.x;
    float4 z = make_float4(0.f, 0.f, 0.f, 0.f);
    for (; i < n4; i += stride) out[i] = z;
}

__global__ void __launch_bounds__(256) spmm_coo_kernel(
    const void* __restrict__ indices, const float* __restrict__ vals,
    const float* __restrict__ b, float* __restrict__ out, int E)
{
    int warp = (int)((blockIdx.x * (long long)blockDim.x + threadIdx.x) >> 5);
    int lane = threadIdx.x & 31;
    if (warp >= E) return;
    int r = load_row(indices, warp, E);
    int c = load_col(indices, warp, E);
    float v = __ldg(vals + warp);
    const float4* brow = reinterpret_cast<const float4*>(b) + (long long)c * (FEAT_D / 4);
    float4 bv = __ldg(brow + lane);
    float* dst = out + (long long)r * FEAT_D + lane * 4;
    asm volatile("red.global.add.v4.f32 [%0], {%1, %2, %3, %4};"
                 :: "l"(dst), "f"(bv.x * v), "f"(bv.y * v),
                    "f"(bv.z * v), "f"(bv.w * v) : "memory");
}

extern "C" void kernel_launch(void* const* d_in, const int* in_sizes, int n_in,
                              void* d_out, int out_size)
{
    const void*  indices = d_in[0];
    const float* vals    = (const float*)d_in[1];
    const float* b       = (const float*)d_in[n_in - 1];

    int E = in_sizes[1];
    int n = out_size / FEAT_D;
    float* out = (float*)d_out;

    bool ok = (E <= E_MAX) && (n <= N_MAX) && ((long long)E <= (long long)n * 40);

    if (ok) {
        init_kernel<<<64, 256>>>((const int*)indices, n);
        build_kernel<<<BUILD_BLOCKS, 256>>>(indices, vals, b, E, n);
        int blocks = (n + 7) / 8;
        spmm_bucket_kernel<<<blocks, 256>>>(out, n);
        ovf_kernel<<<8, 128>>>(b, out);
    } else {
        init_kernel<<<1, 32>>>((const int*)indices, 0);
        zero_out_kernel<<<1184, 256>>>(reinterpret_cast<float4*>(out),
                                       (long long)out_size / 4);
        long long total_threads = (long long)E * 32;
        long long blocks = (total_threads + 255) / 256;
        spmm_coo_kernel<<<(unsigned int)blocks, 256>>>(indices, vals, b, out, E);
    }
}